// round 13
// baseline (speedup 1.0000x reference)
#include <cuda_runtime.h>
#include <cuda_fp16.h>
#include <math.h>
#include <stdint.h>

#define BH    32
#define NSEQ  4096
#define DDIM  64
#define MDIM  256
#define LCOND 256
#define CSZ   64
#define NCH   60          // (4096-256)/64
#define DN    0.35355339059327373f   // 64^-0.25
#define DIAGC 0.0625f                // dn^2 * 0.5
#define KEPS  1e-4f
#define SEPS2 1.6e-5f     // SCAN_EPS / RATIO  (RATIO removed; cancels)
#define FP2   36          // u32 row stride for 64-half tiles
#define FPW   132         // u32 row stride for 256-half (full) tiles, 16B-aligned

// ---------------- scratch ----------------
__device__ __align__(16) __half g_qp[BH*NSEQ*MDIM];      // exp(...)+KEPS
__device__ __align__(16) __half g_kp[BH*NSEQ*MDIM];      // E = exp(dd-diag-bmax_blk)
__device__ __align__(16) __half g_S [BH*NCH*MDIM*DDIM];  // [e][m] prefix ctx
__device__ float g_Z [BH*NCH*MDIM];
__device__ __align__(16) __half g_Scond[BH*MDIM*DDIM];
__device__ float g_Zcond[BH*MDIM];
__device__ uint32_t g_P2[8192];        // DN*proj, half2 pairs, PAIR-ORDER swizzled
__device__ float g_bmax[1024];
__device__ unsigned g_kmax_bits;

__device__ __forceinline__ unsigned enc_f(float f){
    unsigned u = __float_as_uint(f);
    return (u & 0x80000000u) ? ~u : (u | 0x80000000u);
}
__device__ __forceinline__ float dec_f(unsigned e){
    return (e & 0x80000000u) ? __uint_as_float(e & 0x7FFFFFFFu)
                             : __uint_as_float(~e);
}
__device__ __forceinline__ uint32_t packh2(float a, float b){
    __half2 h = __floats2half2_rn(a, b);
    return *reinterpret_cast<uint32_t*>(&h);
}
__device__ __forceinline__ float2 unph2(uint32_t u){
    __half2 h = *reinterpret_cast<__half2*>(&u);
    return __half22float2(h);
}
__device__ __forceinline__ void mma_f16(float c[4],
        uint32_t a0,uint32_t a1,uint32_t a2,uint32_t a3,
        uint32_t b0,uint32_t b1){
    asm volatile("mma.sync.aligned.m16n8k16.row.col.f32.f16.f16.f32 "
        "{%0,%1,%2,%3}, {%4,%5,%6,%7}, {%8,%9}, {%0,%1,%2,%3};"
        : "+f"(c[0]),"+f"(c[1]),"+f"(c[2]),"+f"(c[3])
        : "r"(a0),"r"(a1),"r"(a2),"r"(a3),"r"(b0),"r"(b1));
}
__device__ __forceinline__ uint32_t smem_u32(const void* p){
    uint32_t a;
    asm("{ .reg .u64 t; cvta.to.shared.u64 t, %1; cvt.u32.u64 %0, t; }"
        : "=r"(a) : "l"(p));
    return a;
}
__device__ __forceinline__ void cpa16(uint32_t dst, const void* src){
    asm volatile("cp.async.cg.shared.global [%0], [%1], 16;" :: "r"(dst), "l"(src));
}
#define CPA_COMMIT() asm volatile("cp.async.commit_group;" ::: "memory")
#define CPA_WAIT0()  asm volatile("cp.async.wait_group 0;" ::: "memory")

// ---------------- prep: pair-order half2 P + reset ----------------
__global__ __launch_bounds__(256) void prep_kernel(const float* __restrict__ proj){
    int i = blockIdx.x*256 + threadIdx.x;      // 0..8191
    if (i == 0) g_kmax_bits = 0u;
    int ntg = i >> 8, s = (i >> 6) & 3, gg = (i >> 3) & 7, slot = i & 7;
    int g = gg ^ s;
    int t4p = ((slot >> 1) ^ ntg) & 3;
    int h = slot & 1;
    int n = ntg*8 + g, kp = s*8 + h*4 + t4p;
    g_P2[i] = packh2(proj[n*64 + kp*2] * DN, proj[n*64 + kp*2 + 1] * DN);
}

// ================= feature kernel (fp16 mma) =================
template<bool IS_Q>
__global__ __launch_bounds__(512) void feat_mma(const float* __restrict__ data){
    extern __shared__ uint32_t smu[];
    uint32_t* sA = smu;            // 4096 u32 frag-order
    uint32_t* sB = smu + 4096;     // 8192 u32 pair-order (cp.async'd)
    __shared__ float rowsq[128];
    __shared__ unsigned rowmx[128];
    __shared__ unsigned bmax;

    int tid = threadIdx.x, lane = tid & 31, warp = tid >> 5;
    int gid = lane >> 2, t4 = lane & 3;
    int rowbase = blockIdx.x * 128;
    if (tid == 0) bmax = 0u;
    if (IS_Q && tid < 128) rowmx[tid] = 0u;

    {
        uint32_t sBA = smem_u32(sB);
        for (int i = tid; i < 2048; i += 512)
            cpa16(sBA + i*16, g_P2 + i*4);
        CPA_COMMIT();
    }
    const float* xg = data + (size_t)rowbase * DDIM;
    {
        int kp2 = lane;
        int s = kp2 >> 3, t4s = kp2 & 3, jk = ((kp2 >> 2) & 1) << 1;
        #pragma unroll
        for (int kl = 0; kl < 8; kl++){
            int r = warp + kl*16;
            float2 x2 = *reinterpret_cast<const float2*>(&xg[r*64 + kp2*2]);
            float sq = x2.x*x2.x + x2.y*x2.y;
            #pragma unroll
            for (int o = 16; o; o >>= 1) sq += __shfl_xor_sync(~0u, sq, o);
            if (lane == 0) rowsq[r] = sq;
            int mt = r >> 4, rr = r & 15;
            int ln = ((rr & 7) << 2) | t4s;
            int j  = (rr >> 3) | jk;
            sA[(mt*4 + s)*128 + ln*4 + j] = packh2(x2.x, x2.y);
        }
    }
    CPA_WAIT0();
    __syncthreads();

    int mh = warp >> 2, nq = warp & 3;
    float c[2][8][4];
    #pragma unroll
    for (int mi = 0; mi < 2; mi++)
        #pragma unroll
        for (int nt = 0; nt < 8; nt++){ c[mi][nt][0]=0.f;c[mi][nt][1]=0.f;c[mi][nt][2]=0.f;c[mi][nt][3]=0.f; }

    #pragma unroll
    for (int s = 0; s < 4; s++){
        uint4 av0 = *reinterpret_cast<uint4*>(&sA[((mh*2  )*4 + s)*128 + lane*4]);
        uint4 av1 = *reinterpret_cast<uint4*>(&sA[((mh*2+1)*4 + s)*128 + lane*4]);
        #pragma unroll
        for (int nt = 0; nt < 8; nt++){
            int ntg = nq*8 + nt;
            uint2 bv = *reinterpret_cast<uint2*>(
                &sB[(ntg*4 + s)*64 + ((gid ^ s) << 3) + ((t4 ^ (nt & 3)) << 1)]);
            mma_f16(c[0][nt], av0.x,av0.y,av0.z,av0.w, bv.x,bv.y);
            mma_f16(c[1][nt], av1.x,av1.y,av1.z,av1.w, bv.x,bv.y);
        }
    }

    if (IS_Q){
        float mx[2][2];
        #pragma unroll
        for (int mi = 0; mi < 2; mi++){
            mx[mi][0] = -3.4e38f; mx[mi][1] = -3.4e38f;
            #pragma unroll
            for (int nt = 0; nt < 8; nt++){
                mx[mi][0] = fmaxf(mx[mi][0], fmaxf(c[mi][nt][0], c[mi][nt][1]));
                mx[mi][1] = fmaxf(mx[mi][1], fmaxf(c[mi][nt][2], c[mi][nt][3]));
            }
            #pragma unroll
            for (int o = 1; o < 4; o <<= 1){
                mx[mi][0] = fmaxf(mx[mi][0], __shfl_xor_sync(~0u, mx[mi][0], o));
                mx[mi][1] = fmaxf(mx[mi][1], __shfl_xor_sync(~0u, mx[mi][1], o));
            }
        }
        if (t4 == 0){
            #pragma unroll
            for (int mi = 0; mi < 2; mi++){
                atomicMax(&rowmx[mh*32 + mi*16 + gid],     enc_f(mx[mi][0]));
                atomicMax(&rowmx[mh*32 + mi*16 + gid + 8], enc_f(mx[mi][1]));
            }
        }
        __syncthreads();
        uint32_t* ogu = reinterpret_cast<uint32_t*>(g_qp + (size_t)rowbase*MDIM);
        #pragma unroll
        for (int mi = 0; mi < 2; mi++){
            int r0 = mh*32 + mi*16 + gid;
            float sub0 = rowsq[r0]*DIAGC   + dec_f(rowmx[r0]);
            float sub1 = rowsq[r0+8]*DIAGC + dec_f(rowmx[r0+8]);
            #pragma unroll
            for (int nt = 0; nt < 8; nt++){
                int colh = nq*32 + nt*4 + t4;
                ogu[(size_t)r0*128 + colh] = packh2(
                    __expf(c[mi][nt][0]-sub0)+KEPS,
                    __expf(c[mi][nt][1]-sub0)+KEPS);
                ogu[(size_t)(r0+8)*128 + colh] = packh2(
                    __expf(c[mi][nt][2]-sub1)+KEPS,
                    __expf(c[mi][nt][3]-sub1)+KEPS);
            }
        }
    } else {
        float mx = -3.4e38f;
        #pragma unroll
        for (int mi = 0; mi < 2; mi++)
            #pragma unroll
            for (int nt = 0; nt < 8; nt++)
                mx = fmaxf(mx, fmaxf(fmaxf(c[mi][nt][0], c[mi][nt][1]),
                                     fmaxf(c[mi][nt][2], c[mi][nt][3])));
        #pragma unroll
        for (int o = 16; o; o >>= 1) mx = fmaxf(mx, __shfl_xor_sync(~0u, mx, o));
        if (lane == 0) atomicMax(&bmax, enc_f(mx));
        __syncthreads();
        float bmaxf = dec_f(bmax);
        if (tid == 0){
            atomicMax(&g_kmax_bits, bmax);
            g_bmax[blockIdx.x] = bmaxf;
        }
        uint32_t* ogu = reinterpret_cast<uint32_t*>(g_kp + (size_t)rowbase*MDIM);
        #pragma unroll
        for (int mi = 0; mi < 2; mi++){
            int r0 = mh*32 + mi*16 + gid;
            float s0 = rowsq[r0]*DIAGC + bmaxf, s1 = rowsq[r0+8]*DIAGC + bmaxf;
            #pragma unroll
            for (int nt = 0; nt < 8; nt++){
                int colh = nq*32 + nt*4 + t4;
                ogu[(size_t)r0*128 + colh] = packh2(
                    __expf(c[mi][nt][0]-s0), __expf(c[mi][nt][1]-s0));
                ogu[(size_t)(r0+8)*128 + colh] = packh2(
                    __expf(c[mi][nt][2]-s1), __expf(c[mi][nt][3]-s1));
            }
        }
    }
}

// ================= chunk states (full 256-m per block, fp16) =================
// kf = E*sblk + KEPS folded into staging. z per thread = full column sum.
__global__ __launch_bounds__(256,2) void chunk_mma(const float* __restrict__ v){
    extern __shared__ uint32_t smu[];
    uint32_t* VT = smu;            // [64 e][FP2] pairs over r (2304 u32)
    uint32_t* KT = smu + 64*FP2;   // pair-order 8192 u32 (256 m)

    int tid = threadIdx.x, lane = tid & 31, warp = tid >> 5;
    int gid = lane >> 2, t4 = lane & 3;
    int bh = blockIdx.y, cidx = blockIdx.x;
    int rowbase, npass;
    __half *Sout; float *Zout;
    if (cidx == 0){
        rowbase = bh*NSEQ; npass = 4;
        Sout = g_Scond + (size_t)bh*MDIM*DDIM;
        Zout = g_Zcond + bh*MDIM;
    } else {
        rowbase = bh*NSEQ + LCOND + (cidx-1)*CSZ; npass = 1;
        Sout = g_S + (size_t)(bh*NCH + cidx-1)*MDIM*DDIM;
        Zout = g_Z + (bh*NCH + cidx-1)*MDIM;
    }
    float kmax = dec_f(g_kmax_bits);

    int eh = warp >> 2, nq = warp & 3;
    float c[2][8][4];
    #pragma unroll
    for (int mi = 0; mi < 2; mi++)
        #pragma unroll
        for (int nt = 0; nt < 8; nt++){ c[mi][nt][0]=0.f;c[mi][nt][1]=0.f;c[mi][nt][2]=0.f;c[mi][nt][3]=0.f; }
    float z = 0.f;

    int m_ntg = tid >> 3, m_g = tid & 7, m_x = m_ntg & 3;
    for (int p = 0; p < npass; p++){
        int r0 = rowbase + p*64;
        float sblk = __expf(g_bmax[r0 >> 7] - kmax);
        __syncthreads();
        const float* vg = v + (size_t)r0*DDIM;
        for (int i = tid; i < 2048; i += 256){
            int rp = i >> 6, e = i & 63;
            VT[e*FP2 + rp] = packh2(vg[rp*128 + e], vg[rp*128 + 64 + e]);
        }
        const __half* kg = g_kp + (size_t)r0*MDIM + tid;
        #pragma unroll 4
        for (int j = 0; j < 32; j++){
            float kf0 = fmaf(__half2float(kg[(size_t)(2*j)*MDIM]),   sblk, KEPS);
            float kf1 = fmaf(__half2float(kg[(size_t)(2*j+1)*MDIM]), sblk, KEPS);
            z += kf0 + kf1;
            int s4 = j >> 3, t4p = j & 3, h = (j >> 2) & 1;
            KT[(m_ntg*4 + s4)*64 + ((m_g ^ s4) << 3) + ((t4p ^ m_x) << 1) + h] = packh2(kf0, kf1);
        }
        __syncthreads();
        #pragma unroll
        for (int s = 0; s < 4; s++){
            int kp0 = s*8, er0 = eh*32;
            uint32_t a00 = VT[(er0+gid   )*FP2 + kp0 + t4];
            uint32_t a01 = VT[(er0+gid+8 )*FP2 + kp0 + t4];
            uint32_t a02 = VT[(er0+gid   )*FP2 + kp0 + t4 + 4];
            uint32_t a03 = VT[(er0+gid+8 )*FP2 + kp0 + t4 + 4];
            uint32_t a10 = VT[(er0+gid+16)*FP2 + kp0 + t4];
            uint32_t a11 = VT[(er0+gid+24)*FP2 + kp0 + t4];
            uint32_t a12 = VT[(er0+gid+16)*FP2 + kp0 + t4 + 4];
            uint32_t a13 = VT[(er0+gid+24)*FP2 + kp0 + t4 + 4];
            #pragma unroll
            for (int nt = 0; nt < 8; nt++){
                int ntg = nq*8 + nt;
                uint2 bv = *reinterpret_cast<uint2*>(
                    &KT[(ntg*4 + s)*64 + ((gid ^ s) << 3) + ((t4 ^ (ntg & 3)) << 1)]);
                mma_f16(c[0][nt], a00,a01,a02,a03, bv.x,bv.y);
                mma_f16(c[1][nt], a10,a11,a12,a13, bv.x,bv.y);
            }
        }
    }
    Zout[tid] = z;
    uint32_t* SoU = reinterpret_cast<uint32_t*>(Sout);
    #pragma unroll
    for (int mi = 0; mi < 2; mi++){
        int r0 = eh*32 + mi*16 + gid;
        #pragma unroll
        for (int nt = 0; nt < 8; nt++){
            int colh = nq*32 + nt*4 + t4;
            SoU[(size_t)r0*128 + colh]     = packh2(c[mi][nt][0], c[mi][nt][1]);
            SoU[(size_t)(r0+8)*128 + colh] = packh2(c[mi][nt][2], c[mi][nt][3]);
        }
    }
}

// ================= exclusive prefix over chunks =================
__global__ __launch_bounds__(256) void prefix_kernel(){
    int idx = blockIdx.x*256 + threadIdx.x;
    const int totS2 = BH*8192;                 // half2 columns
    if (idx < totS2){
        int bh = idx >> 13;
        int j  = idx & 8191;
        float2 acc = unph2(reinterpret_cast<uint32_t*>(g_Scond)[idx]);
        uint32_t* p = reinterpret_cast<uint32_t*>(g_S) + (size_t)bh*NCH*8192 + j;
        #pragma unroll 4
        for (int c = 0; c < NCH; c++){
            uint32_t t = p[(size_t)c*8192];
            p[(size_t)c*8192] = packh2(acc.x, acc.y);
            float2 f = unph2(t);
            acc.x += f.x; acc.y += f.y;
        }
    } else {
        int k2 = idx - totS2;
        int bh = k2 >> 8;
        int j  = k2 & 255;
        float acc = g_Zcond[k2];
        float* p = g_Z + bh*NCH*MDIM + j;
        #pragma unroll 4
        for (int c = 0; c < NCH; c++){
            float t = p[c*MDIM];
            p[c*MDIM] = acc;
            acc += t;
        }
    }
}

// ================= attention output (fp16, single full staging) =================
// Q/S/K staged once at full K=256 width (stride FPW); one wait, one sync,
// then 16 uninterrupted MMA k-steps. Scores affine-fixed: s*accA + KEPS*qsum.
__global__ __launch_bounds__(256,2) void attn_mma(const float* __restrict__ v,
                                                  float* __restrict__ out){
    extern __shared__ uint32_t smu[];
    uint32_t* Qs = smu;                // [64][FPW]
    uint32_t* Ks = smu + 64*FPW;       // K tile ; phase2: V^T pairs
    uint32_t* Ss = smu + 2*64*FPW;     // S tile ; phase2: As pairs
    __shared__ float zps[256];
    __shared__ float den2p[4][64];
    __shared__ float denrow[64];
    __shared__ float qsumS[64];
    __shared__ float invden[64];

    int tid = threadIdx.x, lane = tid & 31, warp = tid >> 5;
    int gid = lane >> 2, t4 = lane & 3;
    int bh = blockIdx.y, cc = blockIdx.x;
    bool is_cond = (cc < 4);
    int rowbase;
    const __half *Sp; const float *zp;
    if (is_cond){
        rowbase = bh*NSEQ + cc*64;
        Sp = g_Scond + (size_t)bh*MDIM*DDIM;
        zp = g_Zcond + bh*MDIM;
    } else {
        int c = cc - 4;
        rowbase = bh*NSEQ + LCOND + c*CSZ;
        Sp = g_S + (size_t)(bh*NCH + c)*MDIM*DDIM;
        zp = g_Z + (bh*NCH + c)*MDIM;
    }
    const __half* Qg = g_qp + (size_t)rowbase*MDIM;
    const __half* Kg = g_kp + (size_t)rowbase*MDIM;
    const float* Vg = v + (size_t)rowbase*DDIM;
    float epsv = is_cond ? 0.f : SEPS2;
    float sblk = __expf(g_bmax[rowbase >> 7] - dec_f(g_kmax_bits));
    uint32_t QsA = smem_u32(Qs), KsA = smem_u32(Ks), SsA = smem_u32(Ss);

    if (tid < 64){ denrow[tid] = 0.f; qsumS[tid] = 0.f; }
    zps[tid] = zp[tid] + epsv;

    // ---- stage everything once ----
    for (int i = tid; i < 2048; i += 256){
        int t = i >> 5, qd = i & 31;
        cpa16(QsA + (t*FPW + qd*4)*4, Qg + (size_t)t*MDIM + qd*8);
        cpa16(SsA + (t*FPW + qd*4)*4, Sp + (size_t)t*MDIM + qd*8);
    }
    if (!is_cond)
        for (int i = tid; i < 2048; i += 256){
            int t = i >> 5, qd = i & 31;
            cpa16(KsA + (t*FPW + qd*4)*4, Kg + (size_t)t*MDIM + qd*8);
        }
    CPA_COMMIT(); CPA_WAIT0();
    __syncthreads();

    int mh = warp >> 2, nq = warp & 3;
    float accO[2][2][4], accA[2][2][4];
    #pragma unroll
    for (int mi = 0; mi < 2; mi++)
        #pragma unroll
        for (int nt = 0; nt < 2; nt++){
            accO[mi][nt][0]=0.f;accO[mi][nt][1]=0.f;accO[mi][nt][2]=0.f;accO[mi][nt][3]=0.f;
            accA[mi][nt][0]=0.f;accA[mi][nt][1]=0.f;accA[mi][nt][2]=0.f;accA[mi][nt][3]=0.f;
        }
    // denominator + qsum (single pass)
    {
        int row = tid & 63, grp = tid >> 6;
        float d = 0.f, qs = 0.f;
        #pragma unroll
        for (int j = 0; j < 32; j++){
            int mp = grp*32 + j;
            float2 f = unph2(Qs[row*FPW + mp]);
            d = fmaf(f.x, zps[2*mp], d);
            d = fmaf(f.y, zps[2*mp+1], d);
            qs += f.x + f.y;
        }
        den2p[grp][row] = d;
        if (!is_cond) atomicAdd(&qsumS[row], qs);
    }
    // ---- main MMA loop, K = 256 (128 pairs), 16 steps ----
    #pragma unroll 4
    for (int s = 0; s < 16; s++){
        int kp0 = s*8, mr = mh*32;
        uint32_t a00 = Qs[(mr+gid   )*FPW + kp0 + t4];
        uint32_t a01 = Qs[(mr+gid+8 )*FPW + kp0 + t4];
        uint32_t a02 = Qs[(mr+gid   )*FPW + kp0 + t4 + 4];
        uint32_t a03 = Qs[(mr+gid+8 )*FPW + kp0 + t4 + 4];
        uint32_t a10 = Qs[(mr+gid+16)*FPW + kp0 + t4];
        uint32_t a11 = Qs[(mr+gid+24)*FPW + kp0 + t4];
        uint32_t a12 = Qs[(mr+gid+16)*FPW + kp0 + t4 + 4];
        uint32_t a13 = Qs[(mr+gid+24)*FPW + kp0 + t4 + 4];
        #pragma unroll
        for (int nt = 0; nt < 2; nt++){
            int n0 = nq*16 + nt*8;
            uint32_t s0 = Ss[(n0+gid)*FPW + kp0 + t4];
            uint32_t s1 = Ss[(n0+gid)*FPW + kp0 + t4 + 4];
            mma_f16(accO[0][nt], a00,a01,a02,a03, s0,s1);
            mma_f16(accO[1][nt], a10,a11,a12,a13, s0,s1);
            if (!is_cond){
                uint32_t b0 = Ks[(n0+gid)*FPW + kp0 + t4];
                uint32_t b1 = Ks[(n0+gid)*FPW + kp0 + t4 + 4];
                mma_f16(accA[0][nt], a00,a01,a02,a03, b0,b1);
                mma_f16(accA[1][nt], a10,a11,a12,a13, b0,b1);
            }
        }
    }
    __syncthreads();

    if (!is_cond){
        #pragma unroll
        for (int mi = 0; mi < 2; mi++){
            int r0 = mh*32 + mi*16 + gid;
            float base0 = KEPS * qsumS[r0], base1 = KEPS * qsumS[r0+8];
            float rs0 = 0.f, rs1 = 0.f;
            #pragma unroll
            for (int nt = 0; nt < 2; nt++){
                int col = nq*16 + nt*8 + t4*2;
                int colh = nq*8 + nt*4 + t4;
                float v00 = (col   <= r0  ) ? fmaf(sblk, accA[mi][nt][0], base0) : 0.f;
                float v01 = (col+1 <= r0  ) ? fmaf(sblk, accA[mi][nt][1], base0) : 0.f;
                float v10 = (col   <= r0+8) ? fmaf(sblk, accA[mi][nt][2], base1) : 0.f;
                float v11 = (col+1 <= r0+8) ? fmaf(sblk, accA[mi][nt][3], base1) : 0.f;
                rs0 += v00 + v01; rs1 += v10 + v11;
                Ss[r0*FPW + colh]     = packh2(v00, v01);
                Ss[(r0+8)*FPW + colh] = packh2(v10, v11);
            }
            atomicAdd(&denrow[r0],   rs0);
            atomicAdd(&denrow[r0+8], rs1);
        }
        for (int i = tid; i < 2048; i += 256){
            int sp = i >> 6, e = i & 63;
            Ks[e*FPW + sp] = packh2(Vg[sp*128 + e], Vg[sp*128 + 64 + e]);
        }
        __syncthreads();
        #pragma unroll
        for (int s = 0; s < 4; s++){
            int kp0 = s*8, mr = mh*32;
            uint32_t a00 = Ss[(mr+gid   )*FPW + kp0 + t4];
            uint32_t a01 = Ss[(mr+gid+8 )*FPW + kp0 + t4];
            uint32_t a02 = Ss[(mr+gid   )*FPW + kp0 + t4 + 4];
            uint32_t a03 = Ss[(mr+gid+8 )*FPW + kp0 + t4 + 4];
            uint32_t a10 = Ss[(mr+gid+16)*FPW + kp0 + t4];
            uint32_t a11 = Ss[(mr+gid+24)*FPW + kp0 + t4];
            uint32_t a12 = Ss[(mr+gid+16)*FPW + kp0 + t4 + 4];
            uint32_t a13 = Ss[(mr+gid+24)*FPW + kp0 + t4 + 4];
            #pragma unroll
            for (int nt = 0; nt < 2; nt++){
                int n0 = nq*16 + nt*8;
                uint32_t b0 = Ks[(n0+gid)*FPW + kp0 + t4];
                uint32_t b1 = Ks[(n0+gid)*FPW + kp0 + t4 + 4];
                mma_f16(accO[0][nt], a00,a01,a02,a03, b0,b1);
                mma_f16(accO[1][nt], a10,a11,a12,a13, b0,b1);
            }
        }
    }
    __syncthreads();
    if (tid < 64){
        float d = denrow[tid] + den2p[0][tid] + den2p[1][tid]
                + den2p[2][tid] + den2p[3][tid];
        invden[tid] = 1.f / d;
    }
    __syncthreads();
    #pragma unroll
    for (int mi = 0; mi < 2; mi++){
        int r0 = mh*32 + mi*16 + gid;
        float i0 = invden[r0], i1 = invden[r0+8];
        #pragma unroll
        for (int nt = 0; nt < 2; nt++){
            int col = nq*16 + nt*8 + t4*2;
            float2 o0 = make_float2(accO[mi][nt][0]*i0, accO[mi][nt][1]*i0);
            float2 o1 = make_float2(accO[mi][nt][2]*i1, accO[mi][nt][3]*i1);
            *reinterpret_cast<float2*>(&out[(size_t)(rowbase+r0  )*DDIM + col]) = o0;
            *reinterpret_cast<float2*>(&out[(size_t)(rowbase+r0+8)*DDIM + col]) = o1;
        }
    }
}

// ================= launch =================
extern "C" void kernel_launch(void* const* d_in, const int* in_sizes, int n_in,
                              void* d_out, int out_size){
    const float* q    = (const float*)d_in[0];
    const float* k    = (const float*)d_in[1];
    const float* v    = (const float*)d_in[2];
    const float* proj = (const float*)d_in[3];
    float* out = (float*)d_out;

    const int FEAT_SMEM  = (4096 + 8192) * 4;       // 49152
    const int CHUNK_SMEM = (64*FP2 + 8192) * 4;     // 41984
    const int ATTN_SMEM  = 3*64*FPW*4;              // 101376
    cudaFuncSetAttribute(feat_mma<true>,  cudaFuncAttributeMaxDynamicSharedMemorySize, FEAT_SMEM);
    cudaFuncSetAttribute(feat_mma<false>, cudaFuncAttributeMaxDynamicSharedMemorySize, FEAT_SMEM);
    cudaFuncSetAttribute(chunk_mma,       cudaFuncAttributeMaxDynamicSharedMemorySize, CHUNK_SMEM);
    cudaFuncSetAttribute(attn_mma,        cudaFuncAttributeMaxDynamicSharedMemorySize, ATTN_SMEM);

    prep_kernel<<<32,256>>>(proj);
    feat_mma<false><<<1024,512,FEAT_SMEM>>>(k);
    feat_mma<true ><<<1024,512,FEAT_SMEM>>>(q);
    chunk_mma<<<dim3(61,32),256,CHUNK_SMEM>>>(v);
    prefix_kernel<<<1056,256>>>();
    attn_mma<<<dim3(64,32),256,ATTN_SMEM>>>(v, out);
}

// round 14
// speedup vs baseline: 1.0813x; 1.0813x over previous
#include <cuda_runtime.h>
#include <cuda_fp16.h>
#include <math.h>
#include <stdint.h>

#define BH    32
#define NSEQ  4096
#define DDIM  64
#define MDIM  256
#define LCOND 256
#define CSZ   64
#define NCH   60          // (4096-256)/64
#define DN    0.35355339059327373f   // 64^-0.25
#define DIAGC 0.0625f                // dn^2 * 0.5
#define KEPS  1e-4f
#define SEPS2 1.6e-5f     // SCAN_EPS / RATIO  (RATIO removed; cancels)
#define FP2   36          // u32 (half2) row stride, conflict-free frag reads

// ---------------- scratch (halves stored ratio-free) ----------------
__device__ __align__(16) __half g_qp[BH*NSEQ*MDIM];      // exp(...)+KEPS
__device__ __align__(16) __half g_kp[BH*NSEQ*MDIM];      // E = exp(dd-diag-bmax_blk)
__device__ __align__(16) __half g_S [BH*NCH*MDIM*DDIM];  // [e][m] prefix ctx
__device__ float g_Z [BH*NCH*MDIM];
__device__ __align__(16) __half g_Scond[BH*MDIM*DDIM];
__device__ float g_Zcond[BH*MDIM];
__device__ uint32_t g_P2[8192];        // DN*proj, half2 pairs, PAIR-ORDER swizzled
__device__ float g_bmax[1024];
__device__ unsigned g_kmax_bits;

__device__ __forceinline__ unsigned enc_f(float f){
    unsigned u = __float_as_uint(f);
    return (u & 0x80000000u) ? ~u : (u | 0x80000000u);
}
__device__ __forceinline__ float dec_f(unsigned e){
    return (e & 0x80000000u) ? __uint_as_float(e & 0x7FFFFFFFu)
                             : __uint_as_float(~e);
}
__device__ __forceinline__ uint32_t packh2(float a, float b){
    __half2 h = __floats2half2_rn(a, b);
    return *reinterpret_cast<uint32_t*>(&h);
}
__device__ __forceinline__ float2 unph2(uint32_t u){
    __half2 h = *reinterpret_cast<__half2*>(&u);
    return __half22float2(h);
}
__device__ __forceinline__ void mma_f16(float c[4],
        uint32_t a0,uint32_t a1,uint32_t a2,uint32_t a3,
        uint32_t b0,uint32_t b1){
    asm volatile("mma.sync.aligned.m16n8k16.row.col.f32.f16.f16.f32 "
        "{%0,%1,%2,%3}, {%4,%5,%6,%7}, {%8,%9}, {%0,%1,%2,%3};"
        : "+f"(c[0]),"+f"(c[1]),"+f"(c[2]),"+f"(c[3])
        : "r"(a0),"r"(a1),"r"(a2),"r"(a3),"r"(b0),"r"(b1));
}
__device__ __forceinline__ uint32_t smem_u32(const void* p){
    uint32_t a;
    asm("{ .reg .u64 t; cvta.to.shared.u64 t, %1; cvt.u32.u64 %0, t; }"
        : "=r"(a) : "l"(p));
    return a;
}
__device__ __forceinline__ void cpa16(uint32_t dst, const void* src){
    asm volatile("cp.async.cg.shared.global [%0], [%1], 16;" :: "r"(dst), "l"(src));
}
#define CPA_COMMIT() asm volatile("cp.async.commit_group;" ::: "memory")
#define CPA_WAIT0()  asm volatile("cp.async.wait_group 0;" ::: "memory")

// ---------------- prep: pair-order half2 P + reset ----------------
__global__ __launch_bounds__(256) void prep_kernel(const float* __restrict__ proj){
    int i = blockIdx.x*256 + threadIdx.x;      // 0..8191
    if (i == 0) g_kmax_bits = 0u;
    int ntg = i >> 8, s = (i >> 6) & 3, gg = (i >> 3) & 7, slot = i & 7;
    int g = gg ^ s;
    int t4p = ((slot >> 1) ^ ntg) & 3;
    int h = slot & 1;
    int n = ntg*8 + g, kp = s*8 + h*4 + t4p;
    g_P2[i] = packh2(proj[n*64 + kp*2] * DN, proj[n*64 + kp*2 + 1] * DN);
}

// ================= feature kernel (fp16 mma) =================
// Block: 128 rows, 16 warps. D[128 x 256] = X @ (DN*P)^T. Register epilogue.
template<bool IS_Q>
__global__ __launch_bounds__(512) void feat_mma(const float* __restrict__ data){
    extern __shared__ uint32_t smu[];
    uint32_t* sA = smu;            // 4096 u32 frag-order (half2 pairs)
    uint32_t* sB = smu + 4096;     // 8192 u32 pair-order (cp.async'd)
    __shared__ float rowsq[128];
    __shared__ unsigned rowmx[128];
    __shared__ unsigned bmax;

    int tid = threadIdx.x, lane = tid & 31, warp = tid >> 5;
    int gid = lane >> 2, t4 = lane & 3;
    int rowbase = blockIdx.x * 128;
    if (tid == 0) bmax = 0u;
    if (IS_Q && tid < 128) rowmx[tid] = 0u;

    {
        uint32_t sBA = smem_u32(sB);
        for (int i = tid; i < 2048; i += 512)
            cpa16(sBA + i*16, g_P2 + i*4);
        CPA_COMMIT();
    }
    const float* xg = data + (size_t)rowbase * DDIM;
    {
        int kp2 = lane;
        int s = kp2 >> 3, t4s = kp2 & 3, jk = ((kp2 >> 2) & 1) << 1;
        #pragma unroll
        for (int kl = 0; kl < 8; kl++){
            int r = warp + kl*16;
            float2 x2 = *reinterpret_cast<const float2*>(&xg[r*64 + kp2*2]);
            float sq = x2.x*x2.x + x2.y*x2.y;
            #pragma unroll
            for (int o = 16; o; o >>= 1) sq += __shfl_xor_sync(~0u, sq, o);
            if (lane == 0) rowsq[r] = sq;
            int mt = r >> 4, rr = r & 15;
            int ln = ((rr & 7) << 2) | t4s;
            int j  = (rr >> 3) | jk;
            sA[(mt*4 + s)*128 + ln*4 + j] = packh2(x2.x, x2.y);
        }
    }
    CPA_WAIT0();
    __syncthreads();

    int mh = warp >> 2, nq = warp & 3;
    float c[2][8][4];
    #pragma unroll
    for (int mi = 0; mi < 2; mi++)
        #pragma unroll
        for (int nt = 0; nt < 8; nt++){ c[mi][nt][0]=0.f;c[mi][nt][1]=0.f;c[mi][nt][2]=0.f;c[mi][nt][3]=0.f; }

    #pragma unroll
    for (int s = 0; s < 4; s++){
        uint4 av0 = *reinterpret_cast<uint4*>(&sA[((mh*2  )*4 + s)*128 + lane*4]);
        uint4 av1 = *reinterpret_cast<uint4*>(&sA[((mh*2+1)*4 + s)*128 + lane*4]);
        #pragma unroll
        for (int nt = 0; nt < 8; nt++){
            int ntg = nq*8 + nt;
            uint2 bv = *reinterpret_cast<uint2*>(
                &sB[(ntg*4 + s)*64 + ((gid ^ s) << 3) + ((t4 ^ (nt & 3)) << 1)]);
            mma_f16(c[0][nt], av0.x,av0.y,av0.z,av0.w, bv.x,bv.y);
            mma_f16(c[1][nt], av1.x,av1.y,av1.z,av1.w, bv.x,bv.y);
        }
    }

    if (IS_Q){
        float mx[2][2];
        #pragma unroll
        for (int mi = 0; mi < 2; mi++){
            mx[mi][0] = -3.4e38f; mx[mi][1] = -3.4e38f;
            #pragma unroll
            for (int nt = 0; nt < 8; nt++){
                mx[mi][0] = fmaxf(mx[mi][0], fmaxf(c[mi][nt][0], c[mi][nt][1]));
                mx[mi][1] = fmaxf(mx[mi][1], fmaxf(c[mi][nt][2], c[mi][nt][3]));
            }
            #pragma unroll
            for (int o = 1; o < 4; o <<= 1){
                mx[mi][0] = fmaxf(mx[mi][0], __shfl_xor_sync(~0u, mx[mi][0], o));
                mx[mi][1] = fmaxf(mx[mi][1], __shfl_xor_sync(~0u, mx[mi][1], o));
            }
        }
        if (t4 == 0){
            #pragma unroll
            for (int mi = 0; mi < 2; mi++){
                atomicMax(&rowmx[mh*32 + mi*16 + gid],     enc_f(mx[mi][0]));
                atomicMax(&rowmx[mh*32 + mi*16 + gid + 8], enc_f(mx[mi][1]));
            }
        }
        __syncthreads();
        uint32_t* ogu = reinterpret_cast<uint32_t*>(g_qp + (size_t)rowbase*MDIM);
        #pragma unroll
        for (int mi = 0; mi < 2; mi++){
            int r0 = mh*32 + mi*16 + gid;
            float sub0 = rowsq[r0]*DIAGC   + dec_f(rowmx[r0]);
            float sub1 = rowsq[r0+8]*DIAGC + dec_f(rowmx[r0+8]);
            #pragma unroll
            for (int nt = 0; nt < 8; nt++){
                int colh = nq*32 + nt*4 + t4;
                ogu[(size_t)r0*128 + colh] = packh2(
                    __expf(c[mi][nt][0]-sub0)+KEPS,
                    __expf(c[mi][nt][1]-sub0)+KEPS);
                ogu[(size_t)(r0+8)*128 + colh] = packh2(
                    __expf(c[mi][nt][2]-sub1)+KEPS,
                    __expf(c[mi][nt][3]-sub1)+KEPS);
            }
        }
    } else {
        float mx = -3.4e38f;
        #pragma unroll
        for (int mi = 0; mi < 2; mi++)
            #pragma unroll
            for (int nt = 0; nt < 8; nt++)
                mx = fmaxf(mx, fmaxf(fmaxf(c[mi][nt][0], c[mi][nt][1]),
                                     fmaxf(c[mi][nt][2], c[mi][nt][3])));
        #pragma unroll
        for (int o = 16; o; o >>= 1) mx = fmaxf(mx, __shfl_xor_sync(~0u, mx, o));
        if (lane == 0) atomicMax(&bmax, enc_f(mx));
        __syncthreads();
        float bmaxf = dec_f(bmax);
        if (tid == 0){
            atomicMax(&g_kmax_bits, bmax);
            g_bmax[blockIdx.x] = bmaxf;
        }
        uint32_t* ogu = reinterpret_cast<uint32_t*>(g_kp + (size_t)rowbase*MDIM);
        #pragma unroll
        for (int mi = 0; mi < 2; mi++){
            int r0 = mh*32 + mi*16 + gid;
            float s0 = rowsq[r0]*DIAGC + bmaxf, s1 = rowsq[r0+8]*DIAGC + bmaxf;
            #pragma unroll
            for (int nt = 0; nt < 8; nt++){
                int colh = nq*32 + nt*4 + t4;
                ogu[(size_t)r0*128 + colh] = packh2(
                    __expf(c[mi][nt][0]-s0), __expf(c[mi][nt][1]-s0));
                ogu[(size_t)(r0+8)*128 + colh] = packh2(
                    __expf(c[mi][nt][2]-s1), __expf(c[mi][nt][3]-s1));
            }
        }
    }
}

// ================= chunk states (m-split, fp16) =================
// kp finalize folded in: kf = E*exp(bmax_blk - kmax) + KEPS during staging.
__global__ __launch_bounds__(256,4) void chunk_mma(const float* __restrict__ v){
    extern __shared__ uint32_t smu[];
    uint32_t* VT = smu;            // [64 e][FP2] pairs over r
    uint32_t* KT = smu + 64*FP2;   // pair-order 4096 u32 (128 m)
    __shared__ float zbuf[256];

    int tid = threadIdx.x, lane = tid & 31, warp = tid >> 5;
    int gid = lane >> 2, t4 = lane & 3;
    int bh = blockIdx.y, cidx = blockIdx.x;
    int mbase = blockIdx.z * 128;
    int rowbase, npass;
    __half *Sout; float *Zout;
    if (cidx == 0){
        rowbase = bh*NSEQ; npass = 4;
        Sout = g_Scond + (size_t)bh*MDIM*DDIM;
        Zout = g_Zcond + bh*MDIM;
    } else {
        rowbase = bh*NSEQ + LCOND + (cidx-1)*CSZ; npass = 1;
        Sout = g_S + (size_t)(bh*NCH + cidx-1)*MDIM*DDIM;
        Zout = g_Z + (bh*NCH + cidx-1)*MDIM;
    }
    float kmax = dec_f(g_kmax_bits);

    int eh = warp >> 2, nq = warp & 3;
    float c[2][4][4];
    #pragma unroll
    for (int mi = 0; mi < 2; mi++)
        #pragma unroll
        for (int nt = 0; nt < 4; nt++){ c[mi][nt][0]=0.f;c[mi][nt][1]=0.f;c[mi][nt][2]=0.f;c[mi][nt][3]=0.f; }
    float z = 0.f;

    int m_local = tid & 127, rbase = (tid >> 7) * 32;
    int m_ntg = m_local >> 3, m_g = m_local & 7, m_x = m_ntg & 3;
    for (int p = 0; p < npass; p++){
        int r0 = rowbase + p*64;
        float sblk = __expf(g_bmax[(r0 + rbase) >> 7] - kmax);
        __syncthreads();
        const float* vg = v + (size_t)r0*DDIM;
        for (int i = tid; i < 2048; i += 256){
            int rp = i >> 6, e = i & 63;
            VT[e*FP2 + rp] = packh2(vg[rp*128 + e], vg[rp*128 + 64 + e]);
        }
        const __half* kg = g_kp + (size_t)(r0 + rbase)*MDIM + mbase + m_local;
        #pragma unroll 4
        for (int j = 0; j < 16; j++){
            float kf0 = fmaf(__half2float(kg[(size_t)(2*j)*MDIM]),   sblk, KEPS);
            float kf1 = fmaf(__half2float(kg[(size_t)(2*j+1)*MDIM]), sblk, KEPS);
            z += kf0 + kf1;
            int rp = (rbase >> 1) + j;
            int s4 = rp >> 3, t4p = rp & 3, h = (rp >> 2) & 1;
            KT[(m_ntg*4 + s4)*64 + ((m_g ^ s4) << 3) + ((t4p ^ m_x) << 1) + h] = packh2(kf0, kf1);
        }
        __syncthreads();
        #pragma unroll
        for (int s = 0; s < 4; s++){
            int kp0 = s*8, er0 = eh*32;
            uint32_t a00 = VT[(er0+gid   )*FP2 + kp0 + t4];
            uint32_t a01 = VT[(er0+gid+8 )*FP2 + kp0 + t4];
            uint32_t a02 = VT[(er0+gid   )*FP2 + kp0 + t4 + 4];
            uint32_t a03 = VT[(er0+gid+8 )*FP2 + kp0 + t4 + 4];
            uint32_t a10 = VT[(er0+gid+16)*FP2 + kp0 + t4];
            uint32_t a11 = VT[(er0+gid+24)*FP2 + kp0 + t4];
            uint32_t a12 = VT[(er0+gid+16)*FP2 + kp0 + t4 + 4];
            uint32_t a13 = VT[(er0+gid+24)*FP2 + kp0 + t4 + 4];
            #pragma unroll
            for (int nt = 0; nt < 4; nt++){
                int ntg = nq*4 + nt;
                uint2 bv = *reinterpret_cast<uint2*>(
                    &KT[(ntg*4 + s)*64 + ((gid ^ s) << 3) + ((t4 ^ (ntg & 3)) << 1)]);
                mma_f16(c[0][nt], a00,a01,a02,a03, bv.x,bv.y);
                mma_f16(c[1][nt], a10,a11,a12,a13, bv.x,bv.y);
            }
        }
    }
    zbuf[tid] = z;
    uint32_t* SoU = reinterpret_cast<uint32_t*>(Sout);
    #pragma unroll
    for (int mi = 0; mi < 2; mi++){
        int r0 = eh*32 + mi*16 + gid;
        #pragma unroll
        for (int nt = 0; nt < 4; nt++){
            int colh = (mbase >> 1) + nq*16 + nt*4 + t4;
            SoU[(size_t)r0*128 + colh]     = packh2(c[mi][nt][0], c[mi][nt][1]);
            SoU[(size_t)(r0+8)*128 + colh] = packh2(c[mi][nt][2], c[mi][nt][3]);
        }
    }
    __syncthreads();
    if (tid < 128) Zout[mbase + tid] = zbuf[tid] + zbuf[tid + 128];
}

// ================= exclusive prefix over chunks =================
__global__ __launch_bounds__(256) void prefix_kernel(){
    int idx = blockIdx.x*256 + threadIdx.x;
    const int totS2 = BH*8192;                 // half2 columns
    if (idx < totS2){
        int bh = idx >> 13;
        int j  = idx & 8191;
        float2 acc = unph2(reinterpret_cast<uint32_t*>(g_Scond)[idx]);
        uint32_t* p = reinterpret_cast<uint32_t*>(g_S) + (size_t)bh*NCH*8192 + j;
        #pragma unroll 4
        for (int c = 0; c < NCH; c++){
            uint32_t t = p[(size_t)c*8192];
            p[(size_t)c*8192] = packh2(acc.x, acc.y);
            float2 f = unph2(t);
            acc.x += f.x; acc.y += f.y;
        }
    } else {
        int k2 = idx - totS2;
        int bh = k2 >> 8;
        int j  = k2 & 255;
        float acc = g_Zcond[k2];
        float* p = g_Z + bh*NCH*MDIM + j;
        #pragma unroll 4
        for (int c = 0; c < NCH; c++){
            float t = p[c*MDIM];
            p[c*MDIM] = acc;
            acc += t;
        }
    }
}

// ================= attention output (fp16) =================
// K tile holds raw E; scores fixed up as s*accA + KEPS*qsum(t).
__global__ __launch_bounds__(256,4) void attn_mma(const float* __restrict__ v,
                                                  float* __restrict__ out){
    extern __shared__ uint32_t smu[];
    uint32_t* Qs = smu;               // [64][FP2]
    uint32_t* Ks = smu + 64*FP2;      // K tile ; phase2: V^T pairs
    uint32_t* Ss = smu + 2*64*FP2;    // S tile ; phase2: As pairs
    __shared__ float zps[64];
    __shared__ float den2p[4][64];
    __shared__ float denrow[64];
    __shared__ float qsumS[64];
    __shared__ float invden[64];

    int tid = threadIdx.x, lane = tid & 31, warp = tid >> 5;
    int gid = lane >> 2, t4 = lane & 3;
    int bh = blockIdx.y, cc = blockIdx.x;
    bool is_cond = (cc < 4);
    int rowbase;
    const __half *Sp; const float *zp;
    if (is_cond){
        rowbase = bh*NSEQ + cc*64;
        Sp = g_Scond + (size_t)bh*MDIM*DDIM;
        zp = g_Zcond + bh*MDIM;
    } else {
        int c = cc - 4;
        rowbase = bh*NSEQ + LCOND + c*CSZ;
        Sp = g_S + (size_t)(bh*NCH + c)*MDIM*DDIM;
        zp = g_Z + (bh*NCH + c)*MDIM;
    }
    const __half* Qg = g_qp + (size_t)rowbase*MDIM;
    const __half* Kg = g_kp + (size_t)rowbase*MDIM;
    const float* Vg = v + (size_t)rowbase*DDIM;
    float epsv = is_cond ? 0.f : SEPS2;
    float sblk = __expf(g_bmax[rowbase >> 7] - dec_f(g_kmax_bits));
    uint32_t QsA = smem_u32(Qs), KsA = smem_u32(Ks), SsA = smem_u32(Ss);

    if (tid < 64){ denrow[tid] = 0.f; qsumS[tid] = 0.f; }

    int mh = warp >> 2, nq = warp & 3;
    float accO[2][2][4], accA[2][2][4];
    #pragma unroll
    for (int mi = 0; mi < 2; mi++)
        #pragma unroll
        for (int nt = 0; nt < 2; nt++){
            accO[mi][nt][0]=0.f;accO[mi][nt][1]=0.f;accO[mi][nt][2]=0.f;accO[mi][nt][3]=0.f;
            accA[mi][nt][0]=0.f;accA[mi][nt][1]=0.f;accA[mi][nt][2]=0.f;accA[mi][nt][3]=0.f;
        }
    float den2 = 0.f;

    for (int mtl = 0; mtl < 4; mtl++){
        int m0 = mtl*64;
        __syncthreads();
        for (int i = tid; i < 512; i += 256){
            int t = i >> 3, qd = (i & 7)*4;
            cpa16(QsA + (t*FP2 + qd)*4, Qg + (size_t)t*MDIM + m0 + qd*2);
            cpa16(SsA + (t*FP2 + qd)*4, Sp + (size_t)t*MDIM + m0 + qd*2);
        }
        if (!is_cond)
            for (int i = tid; i < 512; i += 256){
                int t = i >> 3, qd = (i & 7)*4;
                cpa16(KsA + (t*FP2 + qd)*4, Kg + (size_t)t*MDIM + m0 + qd*2);
            }
        if (tid < 64) zps[tid] = zp[m0 + tid];
        CPA_COMMIT(); CPA_WAIT0();
        __syncthreads();
        {
            int row = tid & 63, grp = tid >> 6;
            float d = 0.f, qs = 0.f;
            #pragma unroll
            for (int j = 0; j < 8; j++){
                int mp = grp*8 + j;
                float2 f = unph2(Qs[row*FP2 + mp]);
                d = fmaf(f.x, zps[2*mp] + epsv, d);
                d = fmaf(f.y, zps[2*mp+1] + epsv, d);
                qs += f.x + f.y;
            }
            den2 += d;
            if (!is_cond) atomicAdd(&qsumS[row], qs);
        }
        #pragma unroll
        for (int s = 0; s < 4; s++){
            int kp0 = s*8, mr = mh*32;
            uint32_t a00 = Qs[(mr+gid   )*FP2 + kp0 + t4];
            uint32_t a01 = Qs[(mr+gid+8 )*FP2 + kp0 + t4];
            uint32_t a02 = Qs[(mr+gid   )*FP2 + kp0 + t4 + 4];
            uint32_t a03 = Qs[(mr+gid+8 )*FP2 + kp0 + t4 + 4];
            uint32_t a10 = Qs[(mr+gid+16)*FP2 + kp0 + t4];
            uint32_t a11 = Qs[(mr+gid+24)*FP2 + kp0 + t4];
            uint32_t a12 = Qs[(mr+gid+16)*FP2 + kp0 + t4 + 4];
            uint32_t a13 = Qs[(mr+gid+24)*FP2 + kp0 + t4 + 4];
            #pragma unroll
            for (int nt = 0; nt < 2; nt++){
                int n0 = nq*16 + nt*8;
                uint32_t s0 = Ss[(n0+gid)*FP2 + kp0 + t4];
                uint32_t s1 = Ss[(n0+gid)*FP2 + kp0 + t4 + 4];
                mma_f16(accO[0][nt], a00,a01,a02,a03, s0,s1);
                mma_f16(accO[1][nt], a10,a11,a12,a13, s0,s1);
                if (!is_cond){
                    uint32_t b0 = Ks[(n0+gid)*FP2 + kp0 + t4];
                    uint32_t b1 = Ks[(n0+gid)*FP2 + kp0 + t4 + 4];
                    mma_f16(accA[0][nt], a00,a01,a02,a03, b0,b1);
                    mma_f16(accA[1][nt], a10,a11,a12,a13, b0,b1);
                }
            }
        }
    }
    __syncthreads();
    den2p[tid >> 6][tid & 63] = den2;

    if (!is_cond){
        #pragma unroll
        for (int mi = 0; mi < 2; mi++){
            int r0 = mh*32 + mi*16 + gid;
            float base0 = KEPS * qsumS[r0], base1 = KEPS * qsumS[r0+8];
            float rs0 = 0.f, rs1 = 0.f;
            #pragma unroll
            for (int nt = 0; nt < 2; nt++){
                int col = nq*16 + nt*8 + t4*2;
                int colh = nq*8 + nt*4 + t4;
                float v00 = (col   <= r0  ) ? fmaf(sblk, accA[mi][nt][0], base0) : 0.f;
                float v01 = (col+1 <= r0  ) ? fmaf(sblk, accA[mi][nt][1], base0) : 0.f;
                float v10 = (col   <= r0+8) ? fmaf(sblk, accA[mi][nt][2], base1) : 0.f;
                float v11 = (col+1 <= r0+8) ? fmaf(sblk, accA[mi][nt][3], base1) : 0.f;
                rs0 += v00 + v01; rs1 += v10 + v11;
                Ss[r0*FP2 + colh]     = packh2(v00, v01);
                Ss[(r0+8)*FP2 + colh] = packh2(v10, v11);
            }
            atomicAdd(&denrow[r0],   rs0);
            atomicAdd(&denrow[r0+8], rs1);
        }
        for (int i = tid; i < 2048; i += 256){
            int sp = i >> 6, e = i & 63;
            Ks[e*FP2 + sp] = packh2(Vg[sp*128 + e], Vg[sp*128 + 64 + e]);
        }
        __syncthreads();
        #pragma unroll
        for (int s = 0; s < 4; s++){
            int kp0 = s*8, mr = mh*32;
            uint32_t a00 = Ss[(mr+gid   )*FP2 + kp0 + t4];
            uint32_t a01 = Ss[(mr+gid+8 )*FP2 + kp0 + t4];
            uint32_t a02 = Ss[(mr+gid   )*FP2 + kp0 + t4 + 4];
            uint32_t a03 = Ss[(mr+gid+8 )*FP2 + kp0 + t4 + 4];
            uint32_t a10 = Ss[(mr+gid+16)*FP2 + kp0 + t4];
            uint32_t a11 = Ss[(mr+gid+24)*FP2 + kp0 + t4];
            uint32_t a12 = Ss[(mr+gid+16)*FP2 + kp0 + t4 + 4];
            uint32_t a13 = Ss[(mr+gid+24)*FP2 + kp0 + t4 + 4];
            #pragma unroll
            for (int nt = 0; nt < 2; nt++){
                int n0 = nq*16 + nt*8;
                uint32_t b0 = Ks[(n0+gid)*FP2 + kp0 + t4];
                uint32_t b1 = Ks[(n0+gid)*FP2 + kp0 + t4 + 4];
                mma_f16(accO[0][nt], a00,a01,a02,a03, b0,b1);
                mma_f16(accO[1][nt], a10,a11,a12,a13, b0,b1);
            }
        }
    }
    __syncthreads();
    if (tid < 64){
        float d = denrow[tid] + den2p[0][tid] + den2p[1][tid]
                + den2p[2][tid] + den2p[3][tid];
        invden[tid] = 1.f / d;
    }
    __syncthreads();
    #pragma unroll
    for (int mi = 0; mi < 2; mi++){
        int r0 = mh*32 + mi*16 + gid;
        float i0 = invden[r0], i1 = invden[r0+8];
        #pragma unroll
        for (int nt = 0; nt < 2; nt++){
            int col = nq*16 + nt*8 + t4*2;
            float2 o0 = make_float2(accO[mi][nt][0]*i0, accO[mi][nt][1]*i0);
            float2 o1 = make_float2(accO[mi][nt][2]*i1, accO[mi][nt][3]*i1);
            *reinterpret_cast<float2*>(&out[(size_t)(rowbase+r0  )*DDIM + col]) = o0;
            *reinterpret_cast<float2*>(&out[(size_t)(rowbase+r0+8)*DDIM + col]) = o1;
        }
    }
}

// ================= launch =================
extern "C" void kernel_launch(void* const* d_in, const int* in_sizes, int n_in,
                              void* d_out, int out_size){
    const float* q    = (const float*)d_in[0];
    const float* k    = (const float*)d_in[1];
    const float* v    = (const float*)d_in[2];
    const float* proj = (const float*)d_in[3];
    float* out = (float*)d_out;

    const int FEAT_SMEM  = (4096 + 8192) * 4;       // 49152
    const int CHUNK_SMEM = (64*FP2 + 4096) * 4;     // 25600
    const int ATTN_SMEM  = 3*64*FP2*4;              // 27648
    cudaFuncSetAttribute(feat_mma<true>,  cudaFuncAttributeMaxDynamicSharedMemorySize, FEAT_SMEM);
    cudaFuncSetAttribute(feat_mma<false>, cudaFuncAttributeMaxDynamicSharedMemorySize, FEAT_SMEM);
    cudaFuncSetAttribute(chunk_mma,       cudaFuncAttributeMaxDynamicSharedMemorySize, CHUNK_SMEM);
    cudaFuncSetAttribute(attn_mma,        cudaFuncAttributeMaxDynamicSharedMemorySize, ATTN_SMEM);

    prep_kernel<<<32,256>>>(proj);
    feat_mma<false><<<1024,512,FEAT_SMEM>>>(k);
    feat_mma<true ><<<1024,512,FEAT_SMEM>>>(q);
    chunk_mma<<<dim3(61,32,2),256,CHUNK_SMEM>>>(v);
    prefix_kernel<<<1056,256>>>();
    attn_mma<<<dim3(64,32),256,ATTN_SMEM>>>(v, out);
}

// round 16
// speedup vs baseline: 1.0899x; 1.0079x over previous
#include <cuda_runtime.h>
#include <cuda_fp16.h>
#include <math.h>
#include <stdint.h>

#define BH    32
#define NSEQ  4096
#define DDIM  64
#define MDIM  256
#define LCOND 256
#define CSZ   64
#define NCH   60          // (4096-256)/64
#define DN    0.35355339059327373f   // 64^-0.25
#define DIAGC 0.0625f                // dn^2 * 0.5
#define KEPS  1e-4f
#define SEPS2 1.6e-5f     // SCAN_EPS / RATIO  (RATIO removed; cancels)
#define FP2   36          // u32 (half2) row stride for cp.async tiles (16B-aligned)
#define FPV   33          // odd stride for scalar-only transposed tiles (conflict-free)

// ---------------- scratch (halves stored ratio-free) ----------------
__device__ __align__(16) __half g_qp[BH*NSEQ*MDIM];      // exp(...)+KEPS
__device__ __align__(16) __half g_kp[BH*NSEQ*MDIM];      // E = exp(dd-diag-bmax_blk)
__device__ __align__(16) __half g_S [BH*NCH*MDIM*DDIM];  // [e][m] prefix ctx
__device__ float g_Z [BH*NCH*MDIM];
__device__ __align__(16) __half g_Scond[BH*MDIM*DDIM];
__device__ float g_Zcond[BH*MDIM];
__device__ uint32_t g_P2[8192];        // DN*proj, half2 pairs, PAIR-ORDER swizzled
__device__ float g_bmax[1024];
__device__ unsigned g_kmax_bits;

__device__ __forceinline__ unsigned enc_f(float f){
    unsigned u = __float_as_uint(f);
    return (u & 0x80000000u) ? ~u : (u | 0x80000000u);
}
__device__ __forceinline__ float dec_f(unsigned e){
    return (e & 0x80000000u) ? __uint_as_float(e & 0x7FFFFFFFu)
                             : __uint_as_float(~e);
}
__device__ __forceinline__ uint32_t packh2(float a, float b){
    __half2 h = __floats2half2_rn(a, b);
    return *reinterpret_cast<uint32_t*>(&h);
}
__device__ __forceinline__ float2 unph2(uint32_t u){
    __half2 h = *reinterpret_cast<__half2*>(&u);
    return __half22float2(h);
}
__device__ __forceinline__ void mma_f16(float c[4],
        uint32_t a0,uint32_t a1,uint32_t a2,uint32_t a3,
        uint32_t b0,uint32_t b1){
    asm volatile("mma.sync.aligned.m16n8k16.row.col.f32.f16.f16.f32 "
        "{%0,%1,%2,%3}, {%4,%5,%6,%7}, {%8,%9}, {%0,%1,%2,%3};"
        : "+f"(c[0]),"+f"(c[1]),"+f"(c[2]),"+f"(c[3])
        : "r"(a0),"r"(a1),"r"(a2),"r"(a3),"r"(b0),"r"(b1));
}
__device__ __forceinline__ uint32_t smem_u32(const void* p){
    uint32_t a;
    asm("{ .reg .u64 t; cvta.to.shared.u64 t, %1; cvt.u32.u64 %0, t; }"
        : "=r"(a) : "l"(p));
    return a;
}
__device__ __forceinline__ void cpa16(uint32_t dst, const void* src){
    asm volatile("cp.async.cg.shared.global [%0], [%1], 16;" :: "r"(dst), "l"(src));
}
#define CPA_COMMIT() asm volatile("cp.async.commit_group;" ::: "memory")
#define CPA_WAIT0()  asm volatile("cp.async.wait_group 0;" ::: "memory")

// ---------------- prep: pair-order half2 P + reset ----------------
__global__ __launch_bounds__(256) void prep_kernel(const float* __restrict__ proj){
    int i = blockIdx.x*256 + threadIdx.x;      // 0..8191
    if (i == 0) g_kmax_bits = 0u;
    int ntg = i >> 8, s = (i >> 6) & 3, gg = (i >> 3) & 7, slot = i & 7;
    int g = gg ^ s;
    int t4p = ((slot >> 1) ^ ntg) & 3;
    int h = slot & 1;
    int n = ntg*8 + g, kp = s*8 + h*4 + t4p;
    g_P2[i] = packh2(proj[n*64 + kp*2] * DN, proj[n*64 + kp*2 + 1] * DN);
}

// ================= feature kernel (fp16 mma) =================
// Block: 128 rows, 16 warps. D[128 x 256] = X @ (DN*P)^T. Register epilogue.
template<bool IS_Q>
__global__ __launch_bounds__(512) void feat_mma(const float* __restrict__ data){
    extern __shared__ uint32_t smu[];
    uint32_t* sA = smu;            // 4096 u32 frag-order (half2 pairs)
    uint32_t* sB = smu + 4096;     // 8192 u32 pair-order (cp.async'd)
    __shared__ float rowsq[128];
    __shared__ unsigned rowmx[128];
    __shared__ unsigned bmax;

    int tid = threadIdx.x, lane = tid & 31, warp = tid >> 5;
    int gid = lane >> 2, t4 = lane & 3;
    int rowbase = blockIdx.x * 128;
    if (tid == 0) bmax = 0u;
    if (IS_Q && tid < 128) rowmx[tid] = 0u;

    {
        uint32_t sBA = smem_u32(sB);
        for (int i = tid; i < 2048; i += 512)
            cpa16(sBA + i*16, g_P2 + i*4);
        CPA_COMMIT();
    }
    const float* xg = data + (size_t)rowbase * DDIM;
    {
        int kp2 = lane;
        int s = kp2 >> 3, t4s = kp2 & 3, jk = ((kp2 >> 2) & 1) << 1;
        #pragma unroll
        for (int kl = 0; kl < 8; kl++){
            int r = warp + kl*16;
            float2 x2 = *reinterpret_cast<const float2*>(&xg[r*64 + kp2*2]);
            float sq = x2.x*x2.x + x2.y*x2.y;
            #pragma unroll
            for (int o = 16; o; o >>= 1) sq += __shfl_xor_sync(~0u, sq, o);
            if (lane == 0) rowsq[r] = sq;
            int mt = r >> 4, rr = r & 15;
            int ln = ((rr & 7) << 2) | t4s;
            int j  = (rr >> 3) | jk;
            sA[(mt*4 + s)*128 + ln*4 + j] = packh2(x2.x, x2.y);
        }
    }
    CPA_WAIT0();
    __syncthreads();

    int mh = warp >> 2, nq = warp & 3;
    float c[2][8][4];
    #pragma unroll
    for (int mi = 0; mi < 2; mi++)
        #pragma unroll
        for (int nt = 0; nt < 8; nt++){ c[mi][nt][0]=0.f;c[mi][nt][1]=0.f;c[mi][nt][2]=0.f;c[mi][nt][3]=0.f; }

    #pragma unroll
    for (int s = 0; s < 4; s++){
        uint4 av0 = *reinterpret_cast<uint4*>(&sA[((mh*2  )*4 + s)*128 + lane*4]);
        uint4 av1 = *reinterpret_cast<uint4*>(&sA[((mh*2+1)*4 + s)*128 + lane*4]);
        #pragma unroll
        for (int nt = 0; nt < 8; nt++){
            int ntg = nq*8 + nt;
            uint2 bv = *reinterpret_cast<uint2*>(
                &sB[(ntg*4 + s)*64 + ((gid ^ s) << 3) + ((t4 ^ (nt & 3)) << 1)]);
            mma_f16(c[0][nt], av0.x,av0.y,av0.z,av0.w, bv.x,bv.y);
            mma_f16(c[1][nt], av1.x,av1.y,av1.z,av1.w, bv.x,bv.y);
        }
    }

    if (IS_Q){
        float mx[2][2];
        #pragma unroll
        for (int mi = 0; mi < 2; mi++){
            mx[mi][0] = -3.4e38f; mx[mi][1] = -3.4e38f;
            #pragma unroll
            for (int nt = 0; nt < 8; nt++){
                mx[mi][0] = fmaxf(mx[mi][0], fmaxf(c[mi][nt][0], c[mi][nt][1]));
                mx[mi][1] = fmaxf(mx[mi][1], fmaxf(c[mi][nt][2], c[mi][nt][3]));
            }
            #pragma unroll
            for (int o = 1; o < 4; o <<= 1){
                mx[mi][0] = fmaxf(mx[mi][0], __shfl_xor_sync(~0u, mx[mi][0], o));
                mx[mi][1] = fmaxf(mx[mi][1], __shfl_xor_sync(~0u, mx[mi][1], o));
            }
        }
        if (t4 == 0){
            #pragma unroll
            for (int mi = 0; mi < 2; mi++){
                atomicMax(&rowmx[mh*32 + mi*16 + gid],     enc_f(mx[mi][0]));
                atomicMax(&rowmx[mh*32 + mi*16 + gid + 8], enc_f(mx[mi][1]));
            }
        }
        __syncthreads();
        uint32_t* ogu = reinterpret_cast<uint32_t*>(g_qp + (size_t)rowbase*MDIM);
        #pragma unroll
        for (int mi = 0; mi < 2; mi++){
            int r0 = mh*32 + mi*16 + gid;
            float sub0 = rowsq[r0]*DIAGC   + dec_f(rowmx[r0]);
            float sub1 = rowsq[r0+8]*DIAGC + dec_f(rowmx[r0+8]);
            #pragma unroll
            for (int nt = 0; nt < 8; nt++){
                int colh = nq*32 + nt*4 + t4;
                ogu[(size_t)r0*128 + colh] = packh2(
                    __expf(c[mi][nt][0]-sub0)+KEPS,
                    __expf(c[mi][nt][1]-sub0)+KEPS);
                ogu[(size_t)(r0+8)*128 + colh] = packh2(
                    __expf(c[mi][nt][2]-sub1)+KEPS,
                    __expf(c[mi][nt][3]-sub1)+KEPS);
            }
        }
    } else {
        float mx = -3.4e38f;
        #pragma unroll
        for (int mi = 0; mi < 2; mi++)
            #pragma unroll
            for (int nt = 0; nt < 8; nt++)
                mx = fmaxf(mx, fmaxf(fmaxf(c[mi][nt][0], c[mi][nt][1]),
                                     fmaxf(c[mi][nt][2], c[mi][nt][3])));
        #pragma unroll
        for (int o = 16; o; o >>= 1) mx = fmaxf(mx, __shfl_xor_sync(~0u, mx, o));
        if (lane == 0) atomicMax(&bmax, enc_f(mx));
        __syncthreads();
        float bmaxf = dec_f(bmax);
        if (tid == 0){
            atomicMax(&g_kmax_bits, bmax);
            g_bmax[blockIdx.x] = bmaxf;
        }
        uint32_t* ogu = reinterpret_cast<uint32_t*>(g_kp + (size_t)rowbase*MDIM);
        #pragma unroll
        for (int mi = 0; mi < 2; mi++){
            int r0 = mh*32 + mi*16 + gid;
            float s0 = rowsq[r0]*DIAGC + bmaxf, s1 = rowsq[r0+8]*DIAGC + bmaxf;
            #pragma unroll
            for (int nt = 0; nt < 8; nt++){
                int colh = nq*32 + nt*4 + t4;
                ogu[(size_t)r0*128 + colh] = packh2(
                    __expf(c[mi][nt][0]-s0), __expf(c[mi][nt][1]-s0));
                ogu[(size_t)(r0+8)*128 + colh] = packh2(
                    __expf(c[mi][nt][2]-s1), __expf(c[mi][nt][3]-s1));
            }
        }
    }
}

// ================= chunk states (m-split, fp16) =================
// kp finalize folded in: kf = E*exp(bmax_blk - kmax) + KEPS during staging.
__global__ __launch_bounds__(256,3) void chunk_mma(const float* __restrict__ v){
    extern __shared__ uint32_t smu[];
    uint32_t* VT = smu;            // [64 e][FPV] pairs over r (conflict-free)
    uint32_t* KT = smu + 64*FPV;   // pair-order 4096 u32 (128 m)
    __shared__ float zbuf[256];

    int tid = threadIdx.x, lane = tid & 31, warp = tid >> 5;
    int gid = lane >> 2, t4 = lane & 3;
    int bh = blockIdx.y, cidx = blockIdx.x;
    int mbase = blockIdx.z * 128;
    int rowbase, npass;
    __half *Sout; float *Zout;
    if (cidx == 0){
        rowbase = bh*NSEQ; npass = 4;
        Sout = g_Scond + (size_t)bh*MDIM*DDIM;
        Zout = g_Zcond + bh*MDIM;
    } else {
        rowbase = bh*NSEQ + LCOND + (cidx-1)*CSZ; npass = 1;
        Sout = g_S + (size_t)(bh*NCH + cidx-1)*MDIM*DDIM;
        Zout = g_Z + (bh*NCH + cidx-1)*MDIM;
    }
    float kmax = dec_f(g_kmax_bits);

    int eh = warp >> 2, nq = warp & 3;
    float c[2][4][4];
    #pragma unroll
    for (int mi = 0; mi < 2; mi++)
        #pragma unroll
        for (int nt = 0; nt < 4; nt++){ c[mi][nt][0]=0.f;c[mi][nt][1]=0.f;c[mi][nt][2]=0.f;c[mi][nt][3]=0.f; }
    float z = 0.f;

    int m_local = tid & 127, rbase = (tid >> 7) * 32;
    int m_ntg = m_local >> 3, m_g = m_local & 7, m_x = m_ntg & 3;
    for (int p = 0; p < npass; p++){
        int r0 = rowbase + p*64;
        float sblk = __expf(g_bmax[(r0 + rbase) >> 7] - kmax);
        __syncthreads();
        const float* vg = v + (size_t)r0*DDIM;
        for (int i = tid; i < 2048; i += 256){
            int rp = i >> 6, e = i & 63;
            VT[e*FPV + rp] = packh2(vg[rp*128 + e], vg[rp*128 + 64 + e]);
        }
        const __half* kg = g_kp + (size_t)(r0 + rbase)*MDIM + mbase + m_local;
        #pragma unroll 4
        for (int j = 0; j < 16; j++){
            float kf0 = fmaf(__half2float(kg[(size_t)(2*j)*MDIM]),   sblk, KEPS);
            float kf1 = fmaf(__half2float(kg[(size_t)(2*j+1)*MDIM]), sblk, KEPS);
            z += kf0 + kf1;
            int rp = (rbase >> 1) + j;
            int s4 = rp >> 3, t4p = rp & 3, h = (rp >> 2) & 1;
            KT[(m_ntg*4 + s4)*64 + ((m_g ^ s4) << 3) + ((t4p ^ m_x) << 1) + h] = packh2(kf0, kf1);
        }
        __syncthreads();
        #pragma unroll
        for (int s = 0; s < 4; s++){
            int kp0 = s*8, er0 = eh*32;
            uint32_t a00 = VT[(er0+gid   )*FPV + kp0 + t4];
            uint32_t a01 = VT[(er0+gid+8 )*FPV + kp0 + t4];
            uint32_t a02 = VT[(er0+gid   )*FPV + kp0 + t4 + 4];
            uint32_t a03 = VT[(er0+gid+8 )*FPV + kp0 + t4 + 4];
            uint32_t a10 = VT[(er0+gid+16)*FPV + kp0 + t4];
            uint32_t a11 = VT[(er0+gid+24)*FPV + kp0 + t4];
            uint32_t a12 = VT[(er0+gid+16)*FPV + kp0 + t4 + 4];
            uint32_t a13 = VT[(er0+gid+24)*FPV + kp0 + t4 + 4];
            #pragma unroll
            for (int nt = 0; nt < 4; nt++){
                int ntg = nq*4 + nt;
                uint2 bv = *reinterpret_cast<uint2*>(
                    &KT[(ntg*4 + s)*64 + ((gid ^ s) << 3) + ((t4 ^ (ntg & 3)) << 1)]);
                mma_f16(c[0][nt], a00,a01,a02,a03, bv.x,bv.y);
                mma_f16(c[1][nt], a10,a11,a12,a13, bv.x,bv.y);
            }
        }
    }
    zbuf[tid] = z;
    uint32_t* SoU = reinterpret_cast<uint32_t*>(Sout);
    #pragma unroll
    for (int mi = 0; mi < 2; mi++){
        int r0 = eh*32 + mi*16 + gid;
        #pragma unroll
        for (int nt = 0; nt < 4; nt++){
            int colh = (mbase >> 1) + nq*16 + nt*4 + t4;
            SoU[(size_t)r0*128 + colh]     = packh2(c[mi][nt][0], c[mi][nt][1]);
            SoU[(size_t)(r0+8)*128 + colh] = packh2(c[mi][nt][2], c[mi][nt][3]);
        }
    }
    __syncthreads();
    if (tid < 128) Zout[mbase + tid] = zbuf[tid] + zbuf[tid + 128];
}

// ================= exclusive prefix over chunks =================
__global__ __launch_bounds__(256) void prefix_kernel(){
    int idx = blockIdx.x*256 + threadIdx.x;
    const int totS2 = BH*8192;                 // half2 columns
    if (idx < totS2){
        int bh = idx >> 13;
        int j  = idx & 8191;
        float2 acc = unph2(reinterpret_cast<uint32_t*>(g_Scond)[idx]);
        uint32_t* p = reinterpret_cast<uint32_t*>(g_S) + (size_t)bh*NCH*8192 + j;
        #pragma unroll 4
        for (int c = 0; c < NCH; c++){
            uint32_t t = p[(size_t)c*8192];
            p[(size_t)c*8192] = packh2(acc.x, acc.y);
            float2 f = unph2(t);
            acc.x += f.x; acc.y += f.y;
        }
    } else {
        int k2 = idx - totS2;
        int bh = k2 >> 8;
        int j  = k2 & 255;
        float acc = g_Zcond[k2];
        float* p = g_Z + bh*NCH*MDIM + j;
        #pragma unroll 4
        for (int c = 0; c < NCH; c++){
            float t = p[c*MDIM];
            p[c*MDIM] = acc;
            acc += t;
        }
    }
}

// ================= attention output (fp16) =================
// K tile holds raw E; scores fixed up as s*accA + KEPS*qsum(t).
__global__ __launch_bounds__(256,4) void attn_mma(const float* __restrict__ v,
                                                  float* __restrict__ out){
    extern __shared__ uint32_t smu[];
    uint32_t* Qs = smu;               // [64][FP2]
    uint32_t* Ks = smu + 64*FP2;      // K tile ; phase2: V^T pairs (stride FPV)
    uint32_t* Ss = smu + 2*64*FP2;    // S tile ; phase2: As pairs
    __shared__ float zps[64];
    __shared__ float den2p[4][64];
    __shared__ float denrow[64];
    __shared__ float qsumS[64];
    __shared__ float invden[64];

    int tid = threadIdx.x, lane = tid & 31, warp = tid >> 5;
    int gid = lane >> 2, t4 = lane & 3;
    int bh = blockIdx.y, cc = blockIdx.x;
    bool is_cond = (cc < 4);
    int rowbase;
    const __half *Sp; const float *zp;
    if (is_cond){
        rowbase = bh*NSEQ + cc*64;
        Sp = g_Scond + (size_t)bh*MDIM*DDIM;
        zp = g_Zcond + bh*MDIM;
    } else {
        int c = cc - 4;
        rowbase = bh*NSEQ + LCOND + c*CSZ;
        Sp = g_S + (size_t)(bh*NCH + c)*MDIM*DDIM;
        zp = g_Z + (bh*NCH + c)*MDIM;
    }
    const __half* Qg = g_qp + (size_t)rowbase*MDIM;
    const __half* Kg = g_kp + (size_t)rowbase*MDIM;
    const float* Vg = v + (size_t)rowbase*DDIM;
    float epsv = is_cond ? 0.f : SEPS2;
    float sblk = __expf(g_bmax[rowbase >> 7] - dec_f(g_kmax_bits));
    uint32_t QsA = smem_u32(Qs), KsA = smem_u32(Ks), SsA = smem_u32(Ss);

    if (tid < 64){ denrow[tid] = 0.f; qsumS[tid] = 0.f; }

    int mh = warp >> 2, nq = warp & 3;
    float accO[2][2][4], accA[2][2][4];
    #pragma unroll
    for (int mi = 0; mi < 2; mi++)
        #pragma unroll
        for (int nt = 0; nt < 2; nt++){
            accO[mi][nt][0]=0.f;accO[mi][nt][1]=0.f;accO[mi][nt][2]=0.f;accO[mi][nt][3]=0.f;
            accA[mi][nt][0]=0.f;accA[mi][nt][1]=0.f;accA[mi][nt][2]=0.f;accA[mi][nt][3]=0.f;
        }
    float den2 = 0.f;

    for (int mtl = 0; mtl < 4; mtl++){
        int m0 = mtl*64;
        __syncthreads();
        for (int i = tid; i < 512; i += 256){
            int t = i >> 3, qd = (i & 7)*4;
            cpa16(QsA + (t*FP2 + qd)*4, Qg + (size_t)t*MDIM + m0 + qd*2);
            cpa16(SsA + (t*FP2 + qd)*4, Sp + (size_t)t*MDIM + m0 + qd*2);
        }
        if (!is_cond)
            for (int i = tid; i < 512; i += 256){
                int t = i >> 3, qd = (i & 7)*4;
                cpa16(KsA + (t*FP2 + qd)*4, Kg + (size_t)t*MDIM + m0 + qd*2);
            }
        if (tid < 64) zps[tid] = zp[m0 + tid];
        CPA_COMMIT(); CPA_WAIT0();
        __syncthreads();
        {
            int row = tid & 63, grp = tid >> 6;
            float d = 0.f, qs = 0.f;
            #pragma unroll
            for (int j = 0; j < 8; j++){
                int mp = grp*8 + j;
                float2 f = unph2(Qs[row*FP2 + mp]);
                d = fmaf(f.x, zps[2*mp] + epsv, d);
                d = fmaf(f.y, zps[2*mp+1] + epsv, d);
                qs += f.x + f.y;
            }
            den2 += d;
            if (!is_cond) atomicAdd(&qsumS[row], qs);
        }
        #pragma unroll
        for (int s = 0; s < 4; s++){
            int kp0 = s*8, mr = mh*32;
            uint32_t a00 = Qs[(mr+gid   )*FP2 + kp0 + t4];
            uint32_t a01 = Qs[(mr+gid+8 )*FP2 + kp0 + t4];
            uint32_t a02 = Qs[(mr+gid   )*FP2 + kp0 + t4 + 4];
            uint32_t a03 = Qs[(mr+gid+8 )*FP2 + kp0 + t4 + 4];
            uint32_t a10 = Qs[(mr+gid+16)*FP2 + kp0 + t4];
            uint32_t a11 = Qs[(mr+gid+24)*FP2 + kp0 + t4];
            uint32_t a12 = Qs[(mr+gid+16)*FP2 + kp0 + t4 + 4];
            uint32_t a13 = Qs[(mr+gid+24)*FP2 + kp0 + t4 + 4];
            #pragma unroll
            for (int nt = 0; nt < 2; nt++){
                int n0 = nq*16 + nt*8;
                uint32_t s0 = Ss[(n0+gid)*FP2 + kp0 + t4];
                uint32_t s1 = Ss[(n0+gid)*FP2 + kp0 + t4 + 4];
                mma_f16(accO[0][nt], a00,a01,a02,a03, s0,s1);
                mma_f16(accO[1][nt], a10,a11,a12,a13, s0,s1);
                if (!is_cond){
                    uint32_t b0 = Ks[(n0+gid)*FP2 + kp0 + t4];
                    uint32_t b1 = Ks[(n0+gid)*FP2 + kp0 + t4 + 4];
                    mma_f16(accA[0][nt], a00,a01,a02,a03, b0,b1);
                    mma_f16(accA[1][nt], a10,a11,a12,a13, b0,b1);
                }
            }
        }
    }
    __syncthreads();
    den2p[tid >> 6][tid & 63] = den2;

    if (!is_cond){
        #pragma unroll
        for (int mi = 0; mi < 2; mi++){
            int r0 = mh*32 + mi*16 + gid;
            float base0 = KEPS * qsumS[r0], base1 = KEPS * qsumS[r0+8];
            float rs0 = 0.f, rs1 = 0.f;
            #pragma unroll
            for (int nt = 0; nt < 2; nt++){
                int col = nq*16 + nt*8 + t4*2;
                int colh = nq*8 + nt*4 + t4;
                float v00 = (col   <= r0  ) ? fmaf(sblk, accA[mi][nt][0], base0) : 0.f;
                float v01 = (col+1 <= r0  ) ? fmaf(sblk, accA[mi][nt][1], base0) : 0.f;
                float v10 = (col   <= r0+8) ? fmaf(sblk, accA[mi][nt][2], base1) : 0.f;
                float v11 = (col+1 <= r0+8) ? fmaf(sblk, accA[mi][nt][3], base1) : 0.f;
                rs0 += v00 + v01; rs1 += v10 + v11;
                Ss[r0*FP2 + colh]     = packh2(v00, v01);
                Ss[(r0+8)*FP2 + colh] = packh2(v10, v11);
            }
            atomicAdd(&denrow[r0],   rs0);
            atomicAdd(&denrow[r0+8], rs1);
        }
        for (int i = tid; i < 2048; i += 256){
            int sp = i >> 6, e = i & 63;
            Ks[e*FPV + sp] = packh2(Vg[sp*128 + e], Vg[sp*128 + 64 + e]);
        }
        __syncthreads();
        #pragma unroll
        for (int s = 0; s < 4; s++){
            int kp0 = s*8, mr = mh*32;
            uint32_t a00 = Ss[(mr+gid   )*FP2 + kp0 + t4];
            uint32_t a01 = Ss[(mr+gid+8 )*FP2 + kp0 + t4];
            uint32_t a02 = Ss[(mr+gid   )*FP2 + kp0 + t4 + 4];
            uint32_t a03 = Ss[(mr+gid+8 )*FP2 + kp0 + t4 + 4];
            uint32_t a10 = Ss[(mr+gid+16)*FP2 + kp0 + t4];
            uint32_t a11 = Ss[(mr+gid+24)*FP2 + kp0 + t4];
            uint32_t a12 = Ss[(mr+gid+16)*FP2 + kp0 + t4 + 4];
            uint32_t a13 = Ss[(mr+gid+24)*FP2 + kp0 + t4 + 4];
            #pragma unroll
            for (int nt = 0; nt < 2; nt++){
                int n0 = nq*16 + nt*8;
                uint32_t b0 = Ks[(n0+gid)*FPV + kp0 + t4];
                uint32_t b1 = Ks[(n0+gid)*FPV + kp0 + t4 + 4];
                mma_f16(accO[0][nt], a00,a01,a02,a03, b0,b1);
                mma_f16(accO[1][nt], a10,a11,a12,a13, b0,b1);
            }
        }
    }
    __syncthreads();
    if (tid < 64){
        float d = denrow[tid] + den2p[0][tid] + den2p[1][tid]
                + den2p[2][tid] + den2p[3][tid];
        invden[tid] = 1.f / d;
    }
    __syncthreads();
    #pragma unroll
    for (int mi = 0; mi < 2; mi++){
        int r0 = mh*32 + mi*16 + gid;
        float i0 = invden[r0], i1 = invden[r0+8];
        #pragma unroll
        for (int nt = 0; nt < 2; nt++){
            int col = nq*16 + nt*8 + t4*2;
            float2 o0 = make_float2(accO[mi][nt][0]*i0, accO[mi][nt][1]*i0);
            float2 o1 = make_float2(accO[mi][nt][2]*i1, accO[mi][nt][3]*i1);
            *reinterpret_cast<float2*>(&out[(size_t)(rowbase+r0  )*DDIM + col]) = o0;
            *reinterpret_cast<float2*>(&out[(size_t)(rowbase+r0+8)*DDIM + col]) = o1;
        }
    }
}

// ================= launch =================
extern "C" void kernel_launch(void* const* d_in, const int* in_sizes, int n_in,
                              void* d_out, int out_size){
    const float* q    = (const float*)d_in[0];
    const float* k    = (const float*)d_in[1];
    const float* v    = (const float*)d_in[2];
    const float* proj = (const float*)d_in[3];
    float* out = (float*)d_out;

    const int FEAT_SMEM  = (4096 + 8192) * 4;       // 49152
    const int CHUNK_SMEM = (64*FPV + 4096) * 4;     // 24832
    const int ATTN_SMEM  = 3*64*FP2*4;              // 27648
    cudaFuncSetAttribute(feat_mma<true>,  cudaFuncAttributeMaxDynamicSharedMemorySize, FEAT_SMEM);
    cudaFuncSetAttribute(feat_mma<false>, cudaFuncAttributeMaxDynamicSharedMemorySize, FEAT_SMEM);
    cudaFuncSetAttribute(chunk_mma,       cudaFuncAttributeMaxDynamicSharedMemorySize, CHUNK_SMEM);
    cudaFuncSetAttribute(attn_mma,        cudaFuncAttributeMaxDynamicSharedMemorySize, ATTN_SMEM);

    prep_kernel<<<32,256>>>(proj);
    feat_mma<false><<<1024,512,FEAT_SMEM>>>(k);
    feat_mma<true ><<<1024,512,FEAT_SMEM>>>(q);
    chunk_mma<<<dim3(61,32,2),256,CHUNK_SMEM>>>(v);
    prefix_kernel<<<1056,256>>>();
    attn_mma<<<dim3(64,32),256,ATTN_SMEM>>>(v, out);
}